// round 5
// baseline (speedup 1.0000x reference)
#include <cuda_runtime.h>
#include <cstdint>

// GCN_79568564126323: 2-layer GCN, N=200000, E=3200000, dims 4 -> 16 -> 1.
//
// Aggregate-before-matmul, normalization factored out of edge loops:
//   agg[d] = dinv[d]*(sum_{s->d} xs[s] + xs[d]),  xs = x*dinv
//   z = relu(agg@W1+b1)@W2, zs = z*dinv
//   out[d] = dinv[d]*(sum_{s->d} zs[s] + zs[d]) + b2
// Edge passes: 1 random gather + 1 random RED each (f32; sector-bound).
// R5: f32 REDs restored, 8 edges/thread, smem-weight dense @ 4 nodes/thread.

#define N_MAX 200000

__device__ int    g_cnt [N_MAX];   // zero-init; re-zeroed by k_prep each call
__device__ float  g_dinv[N_MAX];
__device__ float4 g_xs  [N_MAX];   // x * dinv
__device__ float4 g_agg [N_MAX];   // f32 aggregate (seeded with self-loop xs)
__device__ float  g_zs  [N_MAX];   // z * dinv

// ---------------------------------------------------------------- helpers

__device__ __forceinline__ void red_v4(float4* p, float4 v) {
    unsigned long long gp = (unsigned long long)__cvta_generic_to_global(p);
    asm volatile("red.global.add.v4.f32 [%0], {%1, %2, %3, %4};"
                 :: "l"(gp), "f"(v.x), "f"(v.y), "f"(v.z), "f"(v.w)
                 : "memory");
}

// ---------------------------------------------------------------- kernels

__global__ void k_count_deg(const int* __restrict__ dst, int e) {
    int i  = blockIdx.x * blockDim.x + threadIdx.x;
    int e8 = e >> 3;
    if (i < e8) {
        int4 d0 = ((const int4*)dst)[2 * i];
        int4 d1 = ((const int4*)dst)[2 * i + 1];
        atomicAdd(&g_cnt[d0.x], 1);
        atomicAdd(&g_cnt[d0.y], 1);
        atomicAdd(&g_cnt[d0.z], 1);
        atomicAdd(&g_cnt[d0.w], 1);
        atomicAdd(&g_cnt[d1.x], 1);
        atomicAdd(&g_cnt[d1.y], 1);
        atomicAdd(&g_cnt[d1.z], 1);
        atomicAdd(&g_cnt[d1.w], 1);
    } else {
        int t = (e8 << 3) + (i - e8);      // tail edges
        if (t < e) atomicAdd(&g_cnt[dst[t]], 1);
    }
}

// dinv = rsqrt(cnt+1); xs = x*dinv; agg seeded with self-loop xs; cnt re-zeroed
__global__ void k_prep(const float4* __restrict__ x, int n) {
    int i = blockIdx.x * blockDim.x + threadIdx.x;
    if (i >= n) return;
    float di = rsqrtf((float)(g_cnt[i] + 1));   // +1 = self loop
    g_cnt[i]  = 0;                              // ready for next replay
    g_dinv[i] = di;
    float4 xv = x[i];
    float4 xs = make_float4(xv.x * di, xv.y * di, xv.z * di, xv.w * di);
    g_xs[i]  = xs;
    g_agg[i] = xs;                              // self-loop contribution
}

// layer-1 edge scatter: agg[d] += xs[s]   (8 edges per thread)
__global__ void k_scatter1(const int* __restrict__ src,
                           const int* __restrict__ dst, int e) {
    int i  = blockIdx.x * blockDim.x + threadIdx.x;
    int e8 = e >> 3;
    if (i < e8) {
        int4 s0 = ((const int4*)src)[2 * i];
        int4 s1 = ((const int4*)src)[2 * i + 1];
        int4 d0 = ((const int4*)dst)[2 * i];
        int4 d1 = ((const int4*)dst)[2 * i + 1];
        float4 v0 = g_xs[s0.x];
        float4 v1 = g_xs[s0.y];
        float4 v2 = g_xs[s0.z];
        float4 v3 = g_xs[s0.w];
        float4 v4 = g_xs[s1.x];
        float4 v5 = g_xs[s1.y];
        float4 v6 = g_xs[s1.z];
        float4 v7 = g_xs[s1.w];
        red_v4(&g_agg[d0.x], v0);
        red_v4(&g_agg[d0.y], v1);
        red_v4(&g_agg[d0.z], v2);
        red_v4(&g_agg[d0.w], v3);
        red_v4(&g_agg[d1.x], v4);
        red_v4(&g_agg[d1.y], v5);
        red_v4(&g_agg[d1.z], v6);
        red_v4(&g_agg[d1.w], v7);
    } else {
        int t = (e8 << 3) + (i - e8);
        if (t < e) red_v4(&g_agg[dst[t]], g_xs[src[t]]);
    }
}

// per-node dense, 4 nodes/thread, weights in smem, j-outer for LDS amortization
__global__ void k_dense(const float* __restrict__ W1,
                        const float* __restrict__ b1,
                        const float* __restrict__ W2,
                        float* __restrict__ out, int n) {
    __shared__ float sW1[64], sb1[16], sW2[16];
    int t = threadIdx.x;
    if (t < 64) sW1[t] = W1[t];
    if (t < 16) { sb1[t] = b1[t]; sW2[t] = W2[t]; }
    __syncthreads();

    int base = blockIdx.x * blockDim.x * 4 + threadIdx.x;
    float ax[4], ay[4], az[4], aw[4], di[4], z[4];
    bool  ok[4];
#pragma unroll
    for (int m = 0; m < 4; m++) {
        int i = base + m * blockDim.x;
        ok[m] = (i < n);
        if (ok[m]) {
            float d  = g_dinv[i];
            float4 a = g_agg[i];
            di[m] = d;
            ax[m] = a.x * d; ay[m] = a.y * d;
            az[m] = a.z * d; aw[m] = a.w * d;
        }
        z[m] = 0.0f;
    }
#pragma unroll
    for (int j = 0; j < 16; j++) {
        float w0 = sW1[j], w1 = sW1[16 + j], w2 = sW1[32 + j], w3 = sW1[48 + j];
        float bb = sb1[j], wz = sW2[j];
#pragma unroll
        for (int m = 0; m < 4; m++) {
            float h = bb;
            h = fmaf(ax[m], w0, h);
            h = fmaf(ay[m], w1, h);
            h = fmaf(az[m], w2, h);
            h = fmaf(aw[m], w3, h);
            h = fmaxf(h, 0.0f);
            z[m] = fmaf(h, wz, z[m]);
        }
    }
#pragma unroll
    for (int m = 0; m < 4; m++) {
        int i = base + m * blockDim.x;
        if (ok[m]) {
            float zs = z[m] * di[m];
            g_zs[i] = zs;
            out[i]  = zs;                       // self-loop contribution
        }
    }
}

// layer-2 edge scatter: out[d] += zs[s]   (8 edges per thread)
__global__ void k_scatter2(const int* __restrict__ src,
                           const int* __restrict__ dst,
                           float* __restrict__ out, int e) {
    int i  = blockIdx.x * blockDim.x + threadIdx.x;
    int e8 = e >> 3;
    if (i < e8) {
        int4 s0 = ((const int4*)src)[2 * i];
        int4 s1 = ((const int4*)src)[2 * i + 1];
        int4 d0 = ((const int4*)dst)[2 * i];
        int4 d1 = ((const int4*)dst)[2 * i + 1];
        float v0 = g_zs[s0.x];
        float v1 = g_zs[s0.y];
        float v2 = g_zs[s0.z];
        float v3 = g_zs[s0.w];
        float v4 = g_zs[s1.x];
        float v5 = g_zs[s1.y];
        float v6 = g_zs[s1.z];
        float v7 = g_zs[s1.w];
        atomicAdd(&out[d0.x], v0);
        atomicAdd(&out[d0.y], v1);
        atomicAdd(&out[d0.z], v2);
        atomicAdd(&out[d0.w], v3);
        atomicAdd(&out[d1.x], v4);
        atomicAdd(&out[d1.y], v5);
        atomicAdd(&out[d1.z], v6);
        atomicAdd(&out[d1.w], v7);
    } else {
        int t = (e8 << 3) + (i - e8);
        if (t < e) atomicAdd(&out[dst[t]], g_zs[src[t]]);
    }
}

// final per-node scale: out = out*dinv + b2
__global__ void k_final(const float* __restrict__ b2,
                        float* __restrict__ out, int n) {
    int i = blockIdx.x * blockDim.x + threadIdx.x;
    if (i < n) out[i] = fmaf(out[i], g_dinv[i], b2[0]);
}

// ---------------------------------------------------------------- launch

extern "C" void kernel_launch(void* const* d_in, const int* in_sizes, int n_in,
                              void* d_out, int out_size) {
    const float* x   = (const float*)d_in[0];   // [N,4] f32
    const int*   ei  = (const int*)d_in[1];     // [2,E] int32
    const float* W1  = (const float*)d_in[2];   // [4,16]
    const float* b1  = (const float*)d_in[3];   // [16]
    const float* W2  = (const float*)d_in[4];   // [16,1]
    const float* b2  = (const float*)d_in[5];   // [1]
    float*       out = (float*)d_out;           // [N,1]

    const int n = in_sizes[0] / 4;
    const int e = in_sizes[1] / 2;
    const int* src = ei;
    const int* dst = ei + e;

    const int T  = 256;
    const int gn = (n + T - 1) / T;
    // edge kernels: e/8 vector threads + (e%8) tail threads
    const int e8 = e >> 3;
    const int et = e8 + (e & 7);
    const int ge = (et + T - 1) / T;
    // dense: 4 nodes per thread
    const int gd = (n + T * 4 - 1) / (T * 4);

    k_count_deg<<<ge, T>>>(dst, e);
    k_prep     <<<gn, T>>>((const float4*)x, n);
    k_scatter1 <<<ge, T>>>(src, dst, e);
    k_dense    <<<gd, T>>>(W1, b1, W2, out, n);
    k_scatter2 <<<ge, T>>>(src, dst, out, e);
    k_final    <<<gn, T>>>(b2, out, n);
}

// round 6
// speedup vs baseline: 1.0414x; 1.0414x over previous
#include <cuda_runtime.h>
#include <cstdint>

// GCN_79568564126323: 2-layer GCN, N=200000, E=3200000, dims 4 -> 16 -> 1.
//
// Aggregate-before-matmul, normalization factored out of edge loops:
//   agg[d] = dinv[d]*(sum_{s->d} xs[s] + xs[d]),  xs = x*dinv
//   z = relu(agg@W1+b1)@W2, zs = z*dinv
//   out[d] = dinv[d]*(sum_{s->d} zs[s] + zs[d]) + b2
//
// R6: scatters back to the proven 4-edge/thread shape (R3), __ldg gathers,
//     dense at 2 nodes/thread with smem weights.

#define N_MAX 200000

__device__ int    g_cnt [N_MAX];   // zero-init; re-zeroed by k_prep each call
__device__ float  g_dinv[N_MAX];
__device__ float4 g_xs  [N_MAX];   // x * dinv
__device__ float4 g_agg [N_MAX];   // f32 aggregate (seeded with self-loop xs)
__device__ float  g_zs  [N_MAX];   // z * dinv

// ---------------------------------------------------------------- helpers

__device__ __forceinline__ void red_v4(float4* p, float4 v) {
    unsigned long long gp = (unsigned long long)__cvta_generic_to_global(p);
    asm volatile("red.global.add.v4.f32 [%0], {%1, %2, %3, %4};"
                 :: "l"(gp), "f"(v.x), "f"(v.y), "f"(v.z), "f"(v.w)
                 : "memory");
}

// ---------------------------------------------------------------- kernels

__global__ void k_count_deg(const int* __restrict__ dst, int e) {
    int i  = blockIdx.x * blockDim.x + threadIdx.x;
    int e4 = e >> 2;
    if (i < e4) {
        int4 d = ((const int4*)dst)[i];
        atomicAdd(&g_cnt[d.x], 1);
        atomicAdd(&g_cnt[d.y], 1);
        atomicAdd(&g_cnt[d.z], 1);
        atomicAdd(&g_cnt[d.w], 1);
    } else {
        int t = (e4 << 2) + (i - e4);      // tail edges
        if (t < e) atomicAdd(&g_cnt[dst[t]], 1);
    }
}

// dinv = rsqrt(cnt+1); xs = x*dinv; agg seeded with self-loop xs; cnt re-zeroed
__global__ void k_prep(const float4* __restrict__ x, int n) {
    int i = blockIdx.x * blockDim.x + threadIdx.x;
    if (i >= n) return;
    float di = rsqrtf((float)(g_cnt[i] + 1));   // +1 = self loop
    g_cnt[i]  = 0;                              // ready for next replay
    g_dinv[i] = di;
    float4 xv = x[i];
    float4 xs = make_float4(xv.x * di, xv.y * di, xv.z * di, xv.w * di);
    g_xs[i]  = xs;
    g_agg[i] = xs;                              // self-loop contribution
}

// layer-1 edge scatter: agg[d] += xs[s]   (4 edges per thread)
__global__ void k_scatter1(const int* __restrict__ src,
                           const int* __restrict__ dst, int e) {
    int i  = blockIdx.x * blockDim.x + threadIdx.x;
    int e4 = e >> 2;
    if (i < e4) {
        int4 s = ((const int4*)src)[i];
        int4 d = ((const int4*)dst)[i];
        float4 v0 = __ldg(&g_xs[s.x]);
        float4 v1 = __ldg(&g_xs[s.y]);
        float4 v2 = __ldg(&g_xs[s.z]);
        float4 v3 = __ldg(&g_xs[s.w]);
        red_v4(&g_agg[d.x], v0);
        red_v4(&g_agg[d.y], v1);
        red_v4(&g_agg[d.z], v2);
        red_v4(&g_agg[d.w], v3);
    } else {
        int t = (e4 << 2) + (i - e4);
        if (t < e) red_v4(&g_agg[dst[t]], __ldg(&g_xs[src[t]]));
    }
}

// per-node dense, 2 nodes/thread, weights in smem, j-outer for LDS amortization
__global__ void k_dense(const float* __restrict__ W1,
                        const float* __restrict__ b1,
                        const float* __restrict__ W2,
                        float* __restrict__ out, int n) {
    __shared__ float sW1[64], sb1[16], sW2[16];
    int t = threadIdx.x;
    if (t < 64) sW1[t] = W1[t];
    if (t < 16) { sb1[t] = b1[t]; sW2[t] = W2[t]; }
    __syncthreads();

    int base = blockIdx.x * blockDim.x * 2 + threadIdx.x;
    float ax[2], ay[2], az[2], aw[2], di[2], z[2];
    bool  ok[2];
#pragma unroll
    for (int m = 0; m < 2; m++) {
        int i = base + m * blockDim.x;
        ok[m] = (i < n);
        z[m]  = 0.0f;
        ax[m] = ay[m] = az[m] = aw[m] = 0.0f;
        di[m] = 0.0f;
        if (ok[m]) {
            float d  = g_dinv[i];
            float4 a = g_agg[i];
            di[m] = d;
            ax[m] = a.x * d; ay[m] = a.y * d;
            az[m] = a.z * d; aw[m] = a.w * d;
        }
    }
#pragma unroll
    for (int j = 0; j < 16; j++) {
        float w0 = sW1[j], w1 = sW1[16 + j], w2 = sW1[32 + j], w3 = sW1[48 + j];
        float bb = sb1[j], wz = sW2[j];
#pragma unroll
        for (int m = 0; m < 2; m++) {
            float h = bb;
            h = fmaf(ax[m], w0, h);
            h = fmaf(ay[m], w1, h);
            h = fmaf(az[m], w2, h);
            h = fmaf(aw[m], w3, h);
            h = fmaxf(h, 0.0f);
            z[m] = fmaf(h, wz, z[m]);
        }
    }
#pragma unroll
    for (int m = 0; m < 2; m++) {
        int i = base + m * blockDim.x;
        if (ok[m]) {
            float zs = z[m] * di[m];
            g_zs[i] = zs;
            out[i]  = zs;                       // self-loop contribution
        }
    }
}

// layer-2 edge scatter: out[d] += zs[s]   (4 edges per thread)
__global__ void k_scatter2(const int* __restrict__ src,
                           const int* __restrict__ dst,
                           float* __restrict__ out, int e) {
    int i  = blockIdx.x * blockDim.x + threadIdx.x;
    int e4 = e >> 2;
    if (i < e4) {
        int4 s = ((const int4*)src)[i];
        int4 d = ((const int4*)dst)[i];
        float v0 = __ldg(&g_zs[s.x]);
        float v1 = __ldg(&g_zs[s.y]);
        float v2 = __ldg(&g_zs[s.z]);
        float v3 = __ldg(&g_zs[s.w]);
        atomicAdd(&out[d.x], v0);
        atomicAdd(&out[d.y], v1);
        atomicAdd(&out[d.z], v2);
        atomicAdd(&out[d.w], v3);
    } else {
        int t = (e4 << 2) + (i - e4);
        if (t < e) atomicAdd(&out[dst[t]], __ldg(&g_zs[src[t]]));
    }
}

// final per-node scale: out = out*dinv + b2
__global__ void k_final(const float* __restrict__ b2,
                        float* __restrict__ out, int n) {
    int i = blockIdx.x * blockDim.x + threadIdx.x;
    if (i < n) out[i] = fmaf(out[i], g_dinv[i], b2[0]);
}

// ---------------------------------------------------------------- launch

extern "C" void kernel_launch(void* const* d_in, const int* in_sizes, int n_in,
                              void* d_out, int out_size) {
    const float* x   = (const float*)d_in[0];   // [N,4] f32
    const int*   ei  = (const int*)d_in[1];     // [2,E] int32
    const float* W1  = (const float*)d_in[2];   // [4,16]
    const float* b1  = (const float*)d_in[3];   // [16]
    const float* W2  = (const float*)d_in[4];   // [16,1]
    const float* b2  = (const float*)d_in[5];   // [1]
    float*       out = (float*)d_out;           // [N,1]

    const int n = in_sizes[0] / 4;
    const int e = in_sizes[1] / 2;
    const int* src = ei;
    const int* dst = ei + e;

    const int T  = 256;
    const int gn = (n + T - 1) / T;
    const int e4 = e >> 2;
    const int et = e4 + (e & 3);
    const int ge = (et + T - 1) / T;
    const int gd = (n + T * 2 - 1) / (T * 2);   // dense: 2 nodes/thread

    k_count_deg<<<ge, T>>>(dst, e);
    k_prep     <<<gn, T>>>((const float4*)x, n);
    k_scatter1 <<<ge, T>>>(src, dst, e);
    k_dense    <<<gd, T>>>(W1, b1, W2, out, n);
    k_scatter2 <<<ge, T>>>(src, dst, out, e);
    k_final    <<<gn, T>>>(b2, out, n);
}